// round 2
// baseline (speedup 1.0000x reference)
#include <cuda_runtime.h>
#include <cuda_fp16.h>

#define A_DIM 256
#define T_DIM 256
#define P2    129            // row pitch in half2 units (258 halves = 516 B): 129 % 32 == 1 -> conflict-free
#define NTH   512
#define ITERS 5

#define SMEM_E_BYTES (A_DIM * P2 * 4)                 // 132096
#define SMEM_U_OFF   (SMEM_E_BYTES)                   // float[256]
#define SMEM_W_OFF   (SMEM_U_OFF + A_DIM * 4)         // float[256]
#define SMEM_P_OFF   (SMEM_W_OFF + T_DIM * 4)         // float[1024] partials
#define SMEM_TOTAL   (SMEM_P_OFF + 1024 * 4)          // 138240 B

__global__ __launch_bounds__(NTH, 1)
void sinkhorn_kernel(const float* __restrict__ logits,
                     const int* __restrict__ free_agents_num,
                     const int* __restrict__ tasks_num,
                     float* __restrict__ out)
{
    extern __shared__ unsigned char sm[];
    half2* E2   = reinterpret_cast<half2*>(sm);
    float* u    = reinterpret_cast<float*>(sm + SMEM_U_OFF);
    float* w    = reinterpret_cast<float*>(sm + SMEM_W_OFF);
    float* part = reinterpret_cast<float*>(sm + SMEM_P_OFF);

    const int b  = blockIdx.x;
    const int t  = threadIdx.x;
    const int na = free_agents_num[b];
    const int nt = tasks_num[b];

    const float4* __restrict__ L4 =
        reinterpret_cast<const float4*>(logits) + (size_t)b * (A_DIM * T_DIM / 4);
    float4* __restrict__ O4 =
        reinterpret_cast<float4*>(out) + (size_t)b * (A_DIM * T_DIM / 4);

    // Degenerate batch: fully masked -> all zeros.
    if (na == 0 || nt == 0) {
        float4 z = make_float4(0.f, 0.f, 0.f, 0.f);
        #pragma unroll
        for (int k = 0; k < (A_DIM * T_DIM / 4) / NTH; ++k)
            O4[t + k * NTH] = z;
        return;
    }

    if (t < T_DIM) w[t] = 1.0f;

    // ---- Phase 1: stream L from HBM, E = mask ? exp(L) : 0, store fp16 to smem ----
    #pragma unroll
    for (int k = 0; k < (A_DIM * T_DIM / 4) / NTH; ++k) {
        int idx = t + k * NTH;
        int i = idx >> 6;            // 64 float4 per row
        int j = (idx & 63) << 2;
        float4 v = L4[idx];
        bool rv = (i < na);
        float e0 = (rv && (j + 0) < nt) ? __expf(v.x) : 0.f;
        float e1 = (rv && (j + 1) < nt) ? __expf(v.y) : 0.f;
        float e2 = (rv && (j + 2) < nt) ? __expf(v.z) : 0.f;
        float e3 = (rv && (j + 3) < nt) ? __expf(v.w) : 0.f;
        half2* row = E2 + i * P2 + (j >> 1);
        row[0] = __floats2half2_rn(e0, e1);
        row[1] = __floats2half2_rn(e2, e3);
    }
    __syncthreads();

    // ---- Phase 2: 5 Sinkhorn iterations, all in smem ----
    for (int it = 0; it < ITERS; ++it) {
        // Row pass: S_i = sum_j E_ij * w_j.  2 threads per row (split j).
        {
            const int i = t & 255;
            const int h = t >> 8;                       // 0..1
            const half2*  row = E2 + i * P2 + h * 64;
            const float2* w2  = reinterpret_cast<const float2*>(w) + h * 64;
            float acc = 0.f;
            #pragma unroll 8
            for (int k = 0; k < 64; ++k) {
                float2 e  = __half22float2(row[k]);     // lanes: distinct banks (129 ≡ 1 mod 32)
                float2 ww = w2[k];                      // broadcast
                acc = fmaf(e.x, ww.x, acc);
                acc = fmaf(e.y, ww.y, acc);
            }
            part[t] = acc;
        }
        __syncthreads();
        if (t < A_DIM) {
            float S = part[t] + part[t + 256];
            u[t] = (t < na) ? 1.0f / S : 0.f;           // invalid rows: u = 0 (kills NaN paths)
        }
        __syncthreads();

        // Col pass: T_j = sum_i E_ij * u_i.  4 threads per column-pair (split i).
        {
            const int jp = t & 127;                     // half2 column index
            const int h  = t >> 7;                      // 0..3
            float ax = 0.f, ay = 0.f;
            #pragma unroll 8
            for (int k = 0; k < 64; ++k) {
                int i = h * 64 + k;
                float2 e = __half22float2(E2[i * P2 + jp]);  // lanes: consecutive jp -> distinct banks
                float uu = u[i];                              // broadcast
                ax = fmaf(e.x, uu, ax);
                ay = fmaf(e.y, uu, ay);
            }
            reinterpret_cast<float2*>(part)[t] = make_float2(ax, ay);
        }
        __syncthreads();
        if (t < 128) {
            const float2* pc = reinterpret_cast<const float2*>(part);
            float2 a0 = pc[t], a1 = pc[t + 128], a2 = pc[t + 256], a3 = pc[t + 384];
            float Tx = (a0.x + a1.x) + (a2.x + a3.x);
            float Ty = (a0.y + a1.y) + (a2.y + a3.y);
            int j0 = 2 * t;
            w[j0]     = (j0 < nt)     ? 1.0f / Tx : 0.f;    // invalid cols: w = 0
            w[j0 + 1] = (j0 + 1 < nt) ? 1.0f / Ty : 0.f;
        }
        __syncthreads();
    }

    // ---- Phase 3: out = E * u_i * w_j * exp(1e-6), stream to HBM ----
    const float C = 1.0000010000005f;  // exp(1e-6)
    #pragma unroll
    for (int k = 0; k < (A_DIM * T_DIM / 4) / NTH; ++k) {
        int idx = t + k * NTH;
        int i  = idx >> 6;
        int j2 = (idx & 63) << 1;                      // half2 index within row
        float2 e01 = __half22float2(E2[i * P2 + j2]);
        float2 e23 = __half22float2(E2[i * P2 + j2 + 1]);
        float ui = u[i] * C;
        int j = j2 << 1;
        float4 r;
        r.x = e01.x * ui * w[j + 0];
        r.y = e01.y * ui * w[j + 1];
        r.z = e23.x * ui * w[j + 2];
        r.w = e23.y * ui * w[j + 3];
        O4[idx] = r;
    }
}

extern "C" void kernel_launch(void* const* d_in, const int* in_sizes, int n_in,
                              void* d_out, int out_size)
{
    const float* logits = (const float*)d_in[0];
    const int*   agents = (const int*)d_in[1];
    const int*   tasks  = (const int*)d_in[2];
    float*       out    = (float*)d_out;
    const int B = in_sizes[1];   // free_agents_num element count = batch

    // Idempotent, called every launch (no static guards). Not a stream op; capture-safe.
    cudaFuncSetAttribute(sinkhorn_kernel,
                         cudaFuncAttributeMaxDynamicSharedMemorySize, SMEM_TOTAL);

    sinkhorn_kernel<<<B, NTH, SMEM_TOTAL>>>(logits, agents, tasks, out);
}

// round 4
// speedup vs baseline: 1.2184x; 1.2184x over previous
#include <cuda_runtime.h>
#include <cuda_fp16.h>

#define T_DIM 256
#define ROWS  128            // rows per CTA (cluster of 2 covers 256)
#define P2    129            // row pitch in half2 (129 % 32 == 1 -> conflict-free both sweeps)
#define NTH   256
#define ITERS 5

#define SMEM_E      (ROWS * P2 * 4)          // 66048 B: 128 x 129 half2
#define OFF_SCR     SMEM_E                   // 2048 B scratch (256 floats / 256 float2 reuse)
#define OFF_EXCH    (OFF_SCR + 2048)         // 2048 B: colsum exchange [2][256] floats
#define OFF_U       (OFF_EXCH + 2048)        // 512 B: u[128]
#define OFF_W       (OFF_U + 512)            // 1024 B: w[256]
#define SMEM_TOTAL  (OFF_W + 1024)           // 71680 B -> 3 CTAs/SM

__global__ __launch_bounds__(NTH, 3) __cluster_dims__(2, 1, 1)
void sinkhorn_kernel(const float* __restrict__ logits,
                     const int* __restrict__ free_agents_num,
                     const int* __restrict__ tasks_num,
                     float* __restrict__ out)
{
    extern __shared__ unsigned char sm[];
    half2*  E2   = reinterpret_cast<half2*>(sm);
    float*  scr  = reinterpret_cast<float*>(sm + OFF_SCR);
    float2* scr2 = reinterpret_cast<float2*>(sm + OFF_SCR);
    float*  exch = reinterpret_cast<float*>(sm + OFF_EXCH);   // [0..255]=rank0, [256..511]=rank1
    float*  u    = reinterpret_cast<float*>(sm + OFF_U);
    float*  w    = reinterpret_cast<float*>(sm + OFF_W);

    const int rank = blockIdx.x & 1;
    const int b    = blockIdx.x >> 1;
    const int t    = threadIdx.x;
    const int na   = free_agents_num[b];
    const int nt   = tasks_num[b];
    const int row0 = rank * ROWS;

    const float4* __restrict__ L4 =
        reinterpret_cast<const float4*>(logits) + (size_t)b * 16384 + (size_t)rank * 8192;
    float4* __restrict__ O4 =
        reinterpret_cast<float4*>(out) + (size_t)b * 16384 + (size_t)rank * 8192;

    // Degenerate batch: fully masked. Both cluster CTAs take this branch (same b),
    // so cluster-barrier counts stay consistent.
    if (na == 0 || nt == 0) {
        float4 z = make_float4(0.f, 0.f, 0.f, 0.f);
        #pragma unroll
        for (int k = 0; k < 8192 / NTH; ++k)
            O4[t + k * NTH] = z;
        return;
    }

    w[t] = 1.0f;   // NTH == T_DIM

    // ---- Phase 1: stream my 128 rows from HBM, E = mask ? exp(L) : 0, fp16 in smem ----
    #pragma unroll 4
    for (int k = 0; k < 8192 / NTH; ++k) {
        int idx = t + k * NTH;
        int i = idx >> 6;                  // local row (64 float4 per row)
        int j = (idx & 63) << 2;
        float4 v = L4[idx];
        bool rv = (row0 + i) < na;
        float e0 = (rv && (j + 0) < nt) ? __expf(v.x) : 0.f;
        float e1 = (rv && (j + 1) < nt) ? __expf(v.y) : 0.f;
        float e2 = (rv && (j + 2) < nt) ? __expf(v.z) : 0.f;
        float e3 = (rv && (j + 3) < nt) ? __expf(v.w) : 0.f;
        half2* row = E2 + i * P2 + (j >> 1);
        row[0] = __floats2half2_rn(e0, e1);
        row[1] = __floats2half2_rn(e2, e3);
    }
    __syncthreads();

    const int  lo   = t & 127;     // row index (row pass) / half2-column index (col pass)
    const int  h    = t >> 7;      // 0..1 split of the reduction dimension
    const unsigned peer = rank ^ 1;

    // Precompute DSMEM address of MY slot in the PEER's exchange buffer.
    unsigned raddr = 0;
    if (t < 128) {
        unsigned laddr = (unsigned)__cvta_generic_to_shared(&exch[rank * 256 + 2 * t]);
        asm("mapa.shared::cluster.u32 %0, %1, %2;" : "=r"(raddr) : "r"(laddr), "r"(peer));
    }

    for (int it = 0; it < ITERS; ++it) {
        // Row pass: S_i = sum_j E_ij w_j ; 2 threads per row.
        {
            const half2*  row = E2 + lo * P2 + h * 64;
            const float2* w2  = reinterpret_cast<const float2*>(w) + h * 64;
            float acc = 0.f;
            #pragma unroll 8
            for (int k = 0; k < 64; ++k) {
                float2 e  = __half22float2(row[k]);   // stride-129 rows: conflict-free
                float2 ww = w2[k];                    // warp-uniform: broadcast
                acc = fmaf(e.x, ww.x, acc);
                acc = fmaf(e.y, ww.y, acc);
            }
            scr[t] = acc;
        }
        __syncthreads();
        if (t < ROWS) {
            float S = scr[t] + scr[t + 128];
            u[t] = (row0 + t < na) ? 1.0f / S : 0.f;   // invalid rows: u = 0
        }
        __syncthreads();

        // Col pass (local partial over my 128 rows): 2 threads per half2-column.
        {
            float ax = 0.f, ay = 0.f;
            #pragma unroll 8
            for (int k = 0; k < 64; ++k) {
                int i = h * 64 + k;
                float2 e = __half22float2(E2[i * P2 + lo]);  // consecutive lo: conflict-free
                float uu = u[i];                              // warp-uniform: broadcast
                ax = fmaf(e.x, uu, ax);
                ay = fmaf(e.y, uu, ay);
            }
            scr2[h * 128 + lo] = make_float2(ax, ay);
        }
        __syncthreads();

        // Reduce my partials; publish to my slot locally AND in the peer's smem.
        if (t < 128) {
            float2 a = scr2[t], c = scr2[t + 128];
            float sx = a.x + c.x, sy = a.y + c.y;
            exch[rank * 256 + 2 * t]     = sx;
            exch[rank * 256 + 2 * t + 1] = sy;
            asm volatile("st.shared::cluster.f32 [%0], %1;"   :: "r"(raddr),     "f"(sx) : "memory");
            asm volatile("st.shared::cluster.f32 [%0+4], %1;" :: "r"(raddr),     "f"(sy) : "memory");
        }
        // Cluster barrier: release my DSMEM stores, acquire the peer's.
        asm volatile("barrier.cluster.arrive.aligned;" ::: "memory");
        asm volatile("barrier.cluster.wait.aligned;"   ::: "memory");

        if (t < 128) {
            int j0 = 2 * t, j1 = j0 + 1;
            float T0 = exch[j0] + exch[256 + j0];
            float T1 = exch[j1] + exch[256 + j1];
            w[j0] = (j0 < nt) ? 1.0f / T0 : 0.f;       // invalid cols: w = 0
            w[j1] = (j1 < nt) ? 1.0f / T1 : 0.f;
        }
        __syncthreads();
    }

    // ---- Phase 3: out = E * u_i * w_j * exp(1e-6), stream my 128 rows to HBM ----
    const float C = 1.0000010000005f;  // exp(1e-6)
    #pragma unroll 4
    for (int k = 0; k < 8192 / NTH; ++k) {
        int idx = t + k * NTH;
        int i  = idx >> 6;
        int j2 = (idx & 63) << 1;
        float2 e01 = __half22float2(E2[i * P2 + j2]);
        float2 e23 = __half22float2(E2[i * P2 + j2 + 1]);
        float ui = u[i] * C;
        int j = j2 << 1;
        float4 r;
        r.x = e01.x * ui * w[j + 0];
        r.y = e01.y * ui * w[j + 1];
        r.z = e23.x * ui * w[j + 2];
        r.w = e23.y * ui * w[j + 3];
        O4[idx] = r;
    }
}

extern "C" void kernel_launch(void* const* d_in, const int* in_sizes, int n_in,
                              void* d_out, int out_size)
{
    const float* logits = (const float*)d_in[0];
    const int*   agents = (const int*)d_in[1];
    const int*   tasks  = (const int*)d_in[2];
    float*       out    = (float*)d_out;
    const int B = in_sizes[1];   // batch = element count of free_agents_num

    cudaFuncSetAttribute(sinkhorn_kernel,
                         cudaFuncAttributeMaxDynamicSharedMemorySize, SMEM_TOTAL);

    sinkhorn_kernel<<<2 * B, NTH, SMEM_TOTAL>>>(logits, agents, tasks, out);
}

// round 10
// speedup vs baseline: 1.3376x; 1.0978x over previous
#include <cuda_runtime.h>
#include <cuda_fp16.h>

#define T_DIM 256
#define ROWS  128            // rows per CTA (cluster of 2 covers 256)
#define P2    129            // row pitch in half2 (129 % 32 == 1 -> conflict-free both sweeps)
#define NTH   256
#define ITERS 5

#define SMEM_E      (ROWS * P2 * 4)          // 66048 B: 128 x 129 half2
#define OFF_SCR     SMEM_E                   // 2048 B scratch (256 floats / 256 float2 reuse)
#define OFF_EXCH    (OFF_SCR + 2048)         // 2048 B: colsum exchange [2][256] floats
#define OFF_U       (OFF_EXCH + 2048)        // 512 B: u[128]
#define OFF_W       (OFF_U + 512)            // 1024 B: w[256]
#define SMEM_TOTAL  (OFF_W + 1024)           // 71680 B -> 3 CTAs/SM

__global__ __launch_bounds__(NTH, 3) __cluster_dims__(2, 1, 1)
void sinkhorn_kernel(const float* __restrict__ logits,
                     const int* __restrict__ free_agents_num,
                     const int* __restrict__ tasks_num,
                     float* __restrict__ out)
{
    extern __shared__ unsigned char sm[];
    half2*  E2   = reinterpret_cast<half2*>(sm);
    float*  scr  = reinterpret_cast<float*>(sm + OFF_SCR);
    float2* scr2 = reinterpret_cast<float2*>(sm + OFF_SCR);
    float*  exch = reinterpret_cast<float*>(sm + OFF_EXCH);   // [0..255]=rank0, [256..511]=rank1
    float*  u    = reinterpret_cast<float*>(sm + OFF_U);
    float*  w    = reinterpret_cast<float*>(sm + OFF_W);

    const int rank = blockIdx.x & 1;
    const int b    = blockIdx.x >> 1;
    const int t    = threadIdx.x;
    const int na   = free_agents_num[b];
    const int nt   = tasks_num[b];
    const int row0 = rank * ROWS;

    const float4* __restrict__ L4 =
        reinterpret_cast<const float4*>(logits) + (size_t)b * 16384 + (size_t)rank * 8192;
    float4* __restrict__ O4 =
        reinterpret_cast<float4*>(out) + (size_t)b * 16384 + (size_t)rank * 8192;

    // Degenerate batch: fully masked. Both cluster CTAs share b -> both take this branch,
    // so cluster-barrier counts stay consistent.
    if (na == 0 || nt == 0) {
        float4 z = make_float4(0.f, 0.f, 0.f, 0.f);
        #pragma unroll
        for (int k = 0; k < 8192 / NTH; ++k)
            O4[t + k * NTH] = z;
        return;
    }

    w[t] = 1.0f;

    // ---- Phase 1: HBM -> E(fp16) in smem; no HBM load issued for masked regions ----
    #pragma unroll 4
    for (int k = 0; k < 8192 / NTH; ++k) {
        int idx = t + k * NTH;
        int i = idx >> 6;                  // local row (64 float4 per row)
        int j = (idx & 63) << 2;
        half2 h01 = __floats2half2_rn(0.f, 0.f);
        half2 h23 = h01;
        if ((row0 + i) < na && j < nt) {
            float4 v = L4[idx];
            float e0 = __expf(v.x);
            float e1 = (j + 1) < nt ? __expf(v.y) : 0.f;
            float e2 = (j + 2) < nt ? __expf(v.z) : 0.f;
            float e3 = (j + 3) < nt ? __expf(v.w) : 0.f;
            h01 = __floats2half2_rn(e0, e1);
            h23 = __floats2half2_rn(e2, e3);
        }
        half2* row = E2 + i * P2 + (j >> 1);
        row[0] = h01;
        row[1] = h23;
    }
    __syncthreads();

    const int  lo = t & 127;   // row index (row pass) / half2-column index (col pass)
    const int  h  = t >> 7;    // 0..1 split of the reduction dimension
    const unsigned peer = rank ^ 1;

    // --- Validity trimming (skipped terms are exactly zero; bit-exact) ---
    const bool rvalid = (row0 + lo) < na;
    const int  clr    = nt - h * 128;                                   // valid cols in my row-pass half
    const int  rtrips = clr >= 128 ? 64 : (clr > 0 ? ((clr + 1) >> 1) : 0);
    const int  nrl    = min(max(na - row0, 0), ROWS);                   // valid local rows
    const int  rl     = nrl - h * 64;                                   // valid rows in my col-pass split
    const int  ctrips = (2 * lo < nt) ? (rl >= 64 ? 64 : (rl > 0 ? rl : 0)) : 0;

    // DSMEM address of MY slot in the PEER's exchange buffer.
    unsigned raddr = 0;
    if (t < 128) {
        unsigned laddr = (unsigned)__cvta_generic_to_shared(&exch[rank * 256 + 2 * t]);
        asm("mapa.shared::cluster.u32 %0, %1, %2;" : "=r"(raddr) : "r"(laddr), "r"(peer));
    }

    for (int it = 0; it < ITERS; ++it) {
        // Row pass: S_i = sum_j E_ij w_j ; 2 threads per row (h splits 128-col halves).
        {
            float acc = 0.f;
            if (rvalid) {
                const half2*  row = E2 + lo * P2 + h * 64;
                const float2* w2  = reinterpret_cast<const float2*>(w) + h * 64;
                #pragma unroll 4
                for (int k = 0; k < rtrips; ++k) {
                    float2 e  = __half22float2(row[k]);   // stride-129 rows: conflict-free
                    float2 ww = w2[k];                    // warp-uniform: broadcast
                    acc = fmaf(e.x, ww.x, acc);
                    acc = fmaf(e.y, ww.y, acc);
                }
            }
            scr[t] = acc;
        }
        __syncthreads();
        if (t < ROWS) {
            float S = scr[t] + scr[t + 128];
            u[t] = (row0 + t < na) ? 1.0f / S : 0.f;   // invalid rows: u = 0
        }
        __syncthreads();

        // Col pass (local partial over my valid rows): 2 threads per half2-column.
        {
            float ax = 0.f, ay = 0.f;
            #pragma unroll 4
            for (int k = 0; k < ctrips; ++k) {
                int i = h * 64 + k;
                float2 e = __half22float2(E2[i * P2 + lo]);  // consecutive lo: conflict-free
                float uu = u[i];                              // warp-uniform: broadcast
                ax = fmaf(e.x, uu, ax);
                ay = fmaf(e.y, uu, ay);
            }
            scr2[h * 128 + lo] = make_float2(ax, ay);         // always written (zeros if trimmed)
        }
        __syncthreads();

        // Reduce my partials; publish to my slot locally AND in the peer's smem.
        if (t < 128) {
            float2 a = scr2[t], c = scr2[t + 128];
            float sx = a.x + c.x, sy = a.y + c.y;
            exch[rank * 256 + 2 * t]     = sx;
            exch[rank * 256 + 2 * t + 1] = sy;
            asm volatile("st.shared::cluster.f32 [%0], %1;"   :: "r"(raddr), "f"(sx) : "memory");
            asm volatile("st.shared::cluster.f32 [%0+4], %1;" :: "r"(raddr), "f"(sy) : "memory");
        }
        // Cluster barrier: release my DSMEM stores, acquire the peer's.
        asm volatile("barrier.cluster.arrive.aligned;" ::: "memory");
        asm volatile("barrier.cluster.wait.aligned;"   ::: "memory");

        if (t < 128) {
            int j0 = 2 * t, j1 = j0 + 1;
            float T0 = exch[j0] + exch[256 + j0];
            float T1 = exch[j1] + exch[256 + j1];
            w[j0] = (j0 < nt) ? 1.0f / T0 : 0.f;       // invalid cols: w = 0
            w[j1] = (j1 < nt) ? 1.0f / T1 : 0.f;
        }
        __syncthreads();
    }

    // ---- Phase 3: out = E * u_i * w_j * exp(1e-6), stream my 128 rows to HBM ----
    const float C = 1.0000010000005f;  // exp(1e-6)
    #pragma unroll 4
    for (int k = 0; k < 8192 / NTH; ++k) {
        int idx = t + k * NTH;
        int i  = idx >> 6;
        int j2 = (idx & 63) << 1;
        float2 e01 = __half22float2(E2[i * P2 + j2]);
        float2 e23 = __half22float2(E2[i * P2 + j2 + 1]);
        float ui = u[i] * C;
        int j = j2 << 1;
        float4 r;
        r.x = e01.x * ui * w[j + 0];
        r.y = e01.y * ui * w[j + 1];
        r.z = e23.x * ui * w[j + 2];
        r.w = e23.y * ui * w[j + 3];
        O4[idx] = r;
    }
}

extern "C" void kernel_launch(void* const* d_in, const int* in_sizes, int n_in,
                              void* d_out, int out_size)
{
    const float* logits = (const float*)d_in[0];
    const int*   agents = (const int*)d_in[1];
    const int*   tasks  = (const int*)d_in[2];
    float*       out    = (float*)d_out;
    const int B = in_sizes[1];   // batch = element count of free_agents_num

    cudaFuncSetAttribute(sinkhorn_kernel,
                         cudaFuncAttributeMaxDynamicSharedMemorySize, SMEM_TOTAL);

    sinkhorn_kernel<<<2 * B, NTH, SMEM_TOTAL>>>(logits, agents, tasks, out);
}

// round 11
// speedup vs baseline: 1.4328x; 1.0712x over previous
#include <cuda_runtime.h>
#include <cuda_fp16.h>

#define ROWS  128            // rows per CTA (cluster of 2 covers 256)
#define P2    129            // row pitch in half2 words; 129 % 32 == 1 -> bank = (i + j) % 32
#define NTH   512
#define ITERS 5

#define SMEM_E      (ROWS * P2 * 4)          // 66048 B
#define OFF_EXCH    SMEM_E                   // float[2][2][256] double-buffered = 4096 B
#define OFF_U       (OFF_EXCH + 4096)        // float[128]
#define OFF_W       (OFF_U + 512)            // float[256]
#define SMEM_TOTAL  (OFF_W + 1024)           // 71680 B -> 3 CTAs/SM

__global__ __launch_bounds__(NTH, 3) __cluster_dims__(2, 1, 1)
void sinkhorn_kernel(const float* __restrict__ logits,
                     const int* __restrict__ free_agents_num,
                     const int* __restrict__ tasks_num,
                     float* __restrict__ out)
{
    extern __shared__ __align__(16) unsigned char sm[];
    half2* E2   = reinterpret_cast<half2*>(sm);
    float* exch = reinterpret_cast<float*>(sm + OFF_EXCH);  // [buf][rank][256]
    float* u    = reinterpret_cast<float*>(sm + OFF_U);
    float* w    = reinterpret_cast<float*>(sm + OFF_W);

    const int rank = blockIdx.x & 1;
    const int b    = blockIdx.x >> 1;
    const int t    = threadIdx.x;
    const int na   = free_agents_num[b];
    const int nt   = tasks_num[b];
    const int row0 = rank * ROWS;

    const float4* __restrict__ L4 =
        reinterpret_cast<const float4*>(logits) + (size_t)b * 16384 + (size_t)rank * 8192;
    float4* __restrict__ O4 =
        reinterpret_cast<float4*>(out) + (size_t)b * 16384 + (size_t)rank * 8192;

    // Degenerate batch: both cluster CTAs share b -> both take this branch (barrier-safe).
    if (na == 0 || nt == 0) {
        float4 z = make_float4(0.f, 0.f, 0.f, 0.f);
        #pragma unroll
        for (int k = 0; k < 8192 / NTH; ++k)
            O4[t + k * NTH] = z;
        return;
    }

    if (t < 256) w[t] = 1.0f;

    // ---- Phase 1: HBM -> E(fp16) in smem; masked regions: zero-fill, no HBM load ----
    #pragma unroll 4
    for (int k = 0; k < 8192 / NTH; ++k) {
        int idx = t + k * NTH;
        int i = idx >> 6;                  // 64 float4 per row
        int j = (idx & 63) << 2;
        half2 h01 = __floats2half2_rn(0.f, 0.f);
        half2 h23 = h01;
        if ((row0 + i) < na && j < nt) {
            float4 v = L4[idx];
            float e0 = __expf(v.x);
            float e1 = (j + 1) < nt ? __expf(v.y) : 0.f;
            float e2 = (j + 2) < nt ? __expf(v.z) : 0.f;
            float e3 = (j + 3) < nt ? __expf(v.w) : 0.f;
            h01 = __floats2half2_rn(e0, e1);
            h23 = __floats2half2_rn(e2, e3);
        }
        half2* row = E2 + i * P2 + (j >> 1);
        row[0] = h01;
        row[1] = h23;
    }
    __syncthreads();

    // 4-way split; same decomposition serves both passes.
    //   Row pass:  thread (rrow, q) sums half2 cols j(k) = 8q + (k&7) + 32*(k>>3), k < rtrips.
    //   Col pass:  thread (jp,  sp) sums rows      i(k) = 8sp + (k&7) + 32*(k>>3), k < ctrips.
    // Banks (word = half2, pitch 129 ≡ 1 mod 32): row pass bank = rrow + 8q + (k&7);
    // col pass bank = jp + 8sp + (k&7) — each warp hits 32 distinct banks. Conflict-free.
    const int rrow = t >> 2, q = t & 3;    // jp == rrow, sp == q
    const bool rvalid = (row0 + rrow) < na;
    const int ntp = (nt + 1) >> 1;                      // valid half2 cols
    const int nrl = min(max(na - row0, 0), ROWS);       // valid local rows
    int rtrips = 0, ctrips = 0;
    #pragma unroll
    for (int m = 0; m < 4; ++m) {
        rtrips += max(0, min(8, ntp - 32 * m - 8 * q));
        ctrips += max(0, min(8, nrl - 32 * m - 8 * q));
    }
    if (!rvalid) rtrips = 0;
    if (2 * rrow >= nt) ctrips = 0;        // jp gate: both cols masked

    // DSMEM address of MY col-sum slot in the PEER's exchange (buffer 0).
    unsigned raddr0;
    {
        unsigned laddr = (unsigned)__cvta_generic_to_shared(&exch[rank * 256 + 2 * rrow]);
        asm("mapa.shared::cluster.u32 %0, %1, %2;" : "=r"(raddr0) : "r"(laddr), "r"(rank ^ 1));
    }
    const half2* Ebase = E2 + rrow * P2;   // row pass base (also jp offset for col pass)

    for (int it = 0; it < ITERS; ++it) {
        const int bufo = (it & 1) * 512;

        // ---- Row pass: S_i = sum_j E_ij * w_j ----
        float S = 0.f;
        #pragma unroll 4
        for (int k = 0; k < rtrips; ++k) {
            int j = 8 * q + (k & 7) + ((k >> 3) << 5);
            float2 e  = __half22float2(Ebase[j]);                     // conflict-free
            float2 ww = *reinterpret_cast<const float2*>(w + 2 * j);  // 2-way max
            S = fmaf(e.x, ww.x, S);
            S = fmaf(e.y, ww.y, S);
        }
        S += __shfl_xor_sync(0xffffffffu, S, 1);
        S += __shfl_xor_sync(0xffffffffu, S, 2);
        if (q == 0) u[rrow] = rvalid ? 1.0f / S : 0.f;
        __syncthreads();

        // ---- Col pass: T_jp partial = sum_i E_i,jp * u_i ----
        float ax = 0.f, ay = 0.f;
        #pragma unroll 4
        for (int k = 0; k < ctrips; ++k) {
            int i = 8 * q + (k & 7) + ((k >> 3) << 5);
            float2 e = __half22float2(E2[i * P2 + rrow]);   // conflict-free
            float uu = u[i];                                 // broadcast within 8-lane groups
            ax = fmaf(e.x, uu, ax);
            ay = fmaf(e.y, uu, ay);
        }
        ax += __shfl_xor_sync(0xffffffffu, ax, 1);
        ay += __shfl_xor_sync(0xffffffffu, ay, 1);
        ax += __shfl_xor_sync(0xffffffffu, ax, 2);
        ay += __shfl_xor_sync(0xffffffffu, ay, 2);
        if (q == 0) {
            exch[bufo + rank * 256 + 2 * rrow]     = ax;
            exch[bufo + rank * 256 + 2 * rrow + 1] = ay;
            unsigned ra = raddr0 + (unsigned)(bufo * 4);
            asm volatile("st.shared::cluster.f32 [%0],   %1;" :: "r"(ra), "f"(ax) : "memory");
            asm volatile("st.shared::cluster.f32 [%0+4], %1;" :: "r"(ra), "f"(ay) : "memory");
        }
        // Cluster barrier: release my DSMEM stores, acquire the peer's.
        asm volatile("barrier.cluster.arrive.aligned;" ::: "memory");
        asm volatile("barrier.cluster.wait.aligned;"   ::: "memory");

        if (t < 128) {
            int j0 = 2 * t, j1 = j0 + 1;
            float T0 = exch[bufo + j0] + exch[bufo + 256 + j0];
            float T1 = exch[bufo + j1] + exch[bufo + 256 + j1];
            w[j0] = (j0 < nt) ? 1.0f / T0 : 0.f;
            w[j1] = (j1 < nt) ? 1.0f / T1 : 0.f;
        }
        __syncthreads();
    }

    // ---- Phase 3: out = E * u_i * w_j * exp(1e-6) -> HBM ----
    const float C = 1.0000010000005f;
    #pragma unroll 4
    for (int k = 0; k < 8192 / NTH; ++k) {
        int idx = t + k * NTH;
        int i  = idx >> 6;
        int j2 = (idx & 63) << 1;
        float2 e01 = __half22float2(E2[i * P2 + j2]);
        float2 e23 = __half22float2(E2[i * P2 + j2 + 1]);
        float ui = u[i] * C;
        int j = j2 << 1;
        float4 r;
        r.x = e01.x * ui * w[j + 0];
        r.y = e01.y * ui * w[j + 1];
        r.z = e23.x * ui * w[j + 2];
        r.w = e23.y * ui * w[j + 3];
        O4[idx] = r;
    }
}

extern "C" void kernel_launch(void* const* d_in, const int* in_sizes, int n_in,
                              void* d_out, int out_size)
{
    const float* logits = (const float*)d_in[0];
    const int*   agents = (const int*)d_in[1];
    const int*   tasks  = (const int*)d_in[2];
    float*       out    = (float*)d_out;
    const int B = in_sizes[1];

    cudaFuncSetAttribute(sinkhorn_kernel,
                         cudaFuncAttributeMaxDynamicSharedMemorySize, SMEM_TOTAL);

    sinkhorn_kernel<<<2 * B, NTH, SMEM_TOTAL>>>(logits, agents, tasks, out);
}

// round 13
// speedup vs baseline: 1.6314x; 1.1386x over previous
#include <cuda_runtime.h>
#include <cuda_fp16.h>

#define ROWS  128            // rows per CTA (cluster of 2 covers 256)
#define P2    129            // row pitch in half2 words; 129 % 32 == 1 -> bank = (i + j) % 32
#define NTH   512
#define ITERS 5

#define SMEM_E      (ROWS * P2 * 4)          // 66048 B
#define OFF_EXCH    SMEM_E                   // float[2][2][256] double-buffered = 4096 B
#define OFF_U       (OFF_EXCH + 4096)        // float[128]
#define OFF_W       (OFF_U + 512)            // float[256]
#define SMEM_TOTAL  (OFF_W + 1024)           // 71680 B -> 3 CTAs/SM

__global__ __launch_bounds__(NTH, 3) __cluster_dims__(2, 1, 1)
void sinkhorn_kernel(const float* __restrict__ logits,
                     const int* __restrict__ free_agents_num,
                     const int* __restrict__ tasks_num,
                     float* __restrict__ out)
{
    extern __shared__ __align__(16) unsigned char sm[];
    half2* E2   = reinterpret_cast<half2*>(sm);
    float* exch = reinterpret_cast<float*>(sm + OFF_EXCH);  // [buf][rank][256]
    float* u    = reinterpret_cast<float*>(sm + OFF_U);
    float* w    = reinterpret_cast<float*>(sm + OFF_W);

    const int rank = blockIdx.x & 1;
    const int b    = blockIdx.x >> 1;
    const int t    = threadIdx.x;
    const int na   = free_agents_num[b];
    const int nt   = tasks_num[b];
    const int row0 = rank * ROWS;

    const float4* __restrict__ L4 =
        reinterpret_cast<const float4*>(logits) + (size_t)b * 16384 + (size_t)rank * 8192;
    float4* __restrict__ O4 =
        reinterpret_cast<float4*>(out) + (size_t)b * 16384 + (size_t)rank * 8192;

    // Degenerate batch: both cluster CTAs share b -> both take this branch (barrier-safe).
    if (na == 0 || nt == 0) {
        float4 z = make_float4(0.f, 0.f, 0.f, 0.f);
        #pragma unroll
        for (int k = 0; k < 8192 / NTH; ++k)
            O4[t + k * NTH] = z;
        return;
    }

    if (t < 256) w[t] = 1.0f;

    // ---- Phase 1: HBM -> E(fp16) in smem; masked regions: zero-fill, no HBM load ----
    #pragma unroll 4
    for (int k = 0; k < 8192 / NTH; ++k) {
        int idx = t + k * NTH;
        int i = idx >> 6;                  // 64 float4 per row
        int j = (idx & 63) << 2;
        half2 h01 = __floats2half2_rn(0.f, 0.f);
        half2 h23 = h01;
        if ((row0 + i) < na && j < nt) {
            float4 v = L4[idx];
            float e0 = __expf(v.x);
            float e1 = (j + 1) < nt ? __expf(v.y) : 0.f;
            float e2 = (j + 2) < nt ? __expf(v.z) : 0.f;
            float e3 = (j + 3) < nt ? __expf(v.w) : 0.f;
            h01 = __floats2half2_rn(e0, e1);
            h23 = __floats2half2_rn(e2, e3);
        }
        half2* row = E2 + i * P2 + (j >> 1);
        row[0] = h01;
        row[1] = h23;
    }
    __syncthreads();

    // 4-way split, block-granular trimming. Thread (rrow, q):
    //   Row pass: sums half2 cols {8q+32m+c : c<8, m<Mr}; Col pass: rows {8q+32m+c : m<Mc}.
    // Overshoot inside a block is exact-zero work (E and w are zero there) -> bit-exact.
    // Banks (word=half2, pitch 129 ≡ 1 mod 32): bank = rrow + 8q + c; per warp rrow spans 8
    // consecutive values, 8q ∈ {0,8,16,24} -> 32 distinct banks. Conflict-free, both sweeps.
    const int rrow = t >> 2, q = t & 3;
    const bool rvalid = (row0 + rrow) < na;
    const int ntp = (nt + 1) >> 1;                       // valid half2 cols
    const int nrl = min(max(na - row0, 0), ROWS);        // valid local rows
    int Mr = (ntp > 8 * q) ? (((ntp - 8 * q - 1) >> 5) + 1) : 0;   // <= 4
    int Mc = (nrl > 8 * q) ? (((nrl - 8 * q - 1) >> 5) + 1) : 0;   // <= 4
    if (!rvalid) Mr = 0;
    if (2 * rrow >= nt) Mc = 0;            // whole column pair masked

    // DSMEM address of MY col-sum slot in the PEER's exchange (buffer 0).
    unsigned raddr0;
    {
        unsigned laddr = (unsigned)__cvta_generic_to_shared(&exch[rank * 256 + 2 * rrow]);
        asm("mapa.shared::cluster.u32 %0, %1, %2;" : "=r"(raddr0) : "r"(laddr), "r"(rank ^ 1));
    }

    const half2*  Er = E2 + rrow * P2 + 8 * q;                     // row-pass base
    const float2* Wr = reinterpret_cast<const float2*>(w) + 8 * q;
    const half2*  Ec = E2 + (8 * q) * P2 + rrow;                   // col-pass base
    const float*  Uc = u + 8 * q;

    for (int it = 0; it < ITERS; ++it) {
        const int bufo = (it & 1) * 512;

        // ---- Row pass: S_i = sum_j E_ij * w_j  (4 accumulators, const offsets) ----
        float a0 = 0.f, a1 = 0.f, a2 = 0.f, a3 = 0.f;
        {
            const half2*  p  = Er;
            const float2* wp = Wr;
            for (int m = 0; m < Mr; ++m) {
                #pragma unroll
                for (int c = 0; c < 8; ++c) {
                    float2 e  = __half22float2(p[c]);   // LDS const-offset, conflict-free
                    float2 ww = wp[c];                  // 8-lane broadcast
                    if (c & 1) { a2 = fmaf(e.x, ww.x, a2); a3 = fmaf(e.y, ww.y, a3); }
                    else       { a0 = fmaf(e.x, ww.x, a0); a1 = fmaf(e.y, ww.y, a1); }
                }
                p += 32; wp += 32;
            }
        }
        float S = (a0 + a2) + (a1 + a3);
        S += __shfl_xor_sync(0xffffffffu, S, 1);
        S += __shfl_xor_sync(0xffffffffu, S, 2);
        if (q == 0) u[rrow] = rvalid ? 1.0f / S : 0.f;
        __syncthreads();

        // ---- Col pass: T_jp partial = sum_i E_i,jp * u_i  (4 accumulators) ----
        float x0 = 0.f, y0 = 0.f, x1 = 0.f, y1 = 0.f;
        {
            const half2* p  = Ec;
            const float* up = Uc;
            for (int m = 0; m < Mc; ++m) {
                #pragma unroll
                for (int c = 0; c < 8; ++c) {
                    float2 e = __half22float2(p[c * P2]);  // const offset c*129
                    float uu = up[c];                       // 8-lane broadcast
                    if (c & 1) { x1 = fmaf(e.x, uu, x1); y1 = fmaf(e.y, uu, y1); }
                    else       { x0 = fmaf(e.x, uu, x0); y0 = fmaf(e.y, uu, y0); }
                }
                p += 32 * P2; up += 32;
            }
        }
        float ax = x0 + x1, ay = y0 + y1;
        ax += __shfl_xor_sync(0xffffffffu, ax, 1);
        ay += __shfl_xor_sync(0xffffffffu, ay, 1);
        ax += __shfl_xor_sync(0xffffffffu, ax, 2);
        ay += __shfl_xor_sync(0xffffffffu, ay, 2);
        if (q == 0) {
            exch[bufo + rank * 256 + 2 * rrow]     = ax;
            exch[bufo + rank * 256 + 2 * rrow + 1] = ay;
            unsigned ra = raddr0 + (unsigned)(bufo * 4);
            asm volatile("st.shared::cluster.f32 [%0],   %1;" :: "r"(ra), "f"(ax) : "memory");
            asm volatile("st.shared::cluster.f32 [%0+4], %1;" :: "r"(ra), "f"(ay) : "memory");
        }
        // Cluster barrier: release my DSMEM stores, acquire the peer's.
        asm volatile("barrier.cluster.arrive.aligned;" ::: "memory");
        asm volatile("barrier.cluster.wait.aligned;"   ::: "memory");

        if (t < 128) {
            int j0 = 2 * t, j1 = j0 + 1;
            float T0 = exch[bufo + j0] + exch[bufo + 256 + j0];
            float T1 = exch[bufo + j1] + exch[bufo + 256 + j1];
            w[j0] = (j0 < nt) ? 1.0f / T0 : 0.f;
            w[j1] = (j1 < nt) ? 1.0f / T1 : 0.f;
        }
        __syncthreads();
    }

    // ---- Phase 3: out = E * u_i * w_j * exp(1e-6) -> HBM ----
    const float C = 1.0000010000005f;
    #pragma unroll 4
    for (int k = 0; k < 8192 / NTH; ++k) {
        int idx = t + k * NTH;
        int i  = idx >> 6;
        int j2 = (idx & 63) << 1;
        float2 e01 = __half22float2(E2[i * P2 + j2]);
        float2 e23 = __half22float2(E2[i * P2 + j2 + 1]);
        float ui = u[i] * C;
        int j = j2 << 1;
        float4 r;
        r.x = e01.x * ui * w[j + 0];
        r.y = e01.y * ui * w[j + 1];
        r.z = e23.x * ui * w[j + 2];
        r.w = e23.y * ui * w[j + 3];
        O4[idx] = r;
    }
}

extern "C" void kernel_launch(void* const* d_in, const int* in_sizes, int n_in,
                              void* d_out, int out_size)
{
    const float* logits = (const float*)d_in[0];
    const int*   agents = (const int*)d_in[1];
    const int*   tasks  = (const int*)d_in[2];
    float*       out    = (float*)d_out;
    const int B = in_sizes[1];

    cudaFuncSetAttribute(sinkhorn_kernel,
                         cudaFuncAttributeMaxDynamicSharedMemorySize, SMEM_TOTAL);

    sinkhorn_kernel<<<2 * B, NTH, SMEM_TOTAL>>>(logits, agents, tasks, out);
}

// round 14
// speedup vs baseline: 1.6421x; 1.0066x over previous
#include <cuda_runtime.h>
#include <cuda_fp16.h>

#define ROWS  128            // rows per CTA (cluster of 2 covers 256)
#define P2    129            // row pitch in half2 words; 129 % 32 == 1 -> bank = (i + j) % 32
#define NTH   512
#define ITERS 5

#define SMEM_E      (ROWS * P2 * 4)          // 66048 B
#define OFF_EXCH    SMEM_E                   // float[2][2][256] double-buffered = 4096 B
#define OFF_U       (OFF_EXCH + 4096)        // float[128]
#define OFF_W       (OFF_U + 512)            // float[256]
#define SMEM_TOTAL  (OFF_W + 1024)           // 71680 B -> 3 CTAs/SM

__global__ __launch_bounds__(NTH, 3) __cluster_dims__(2, 1, 1)
void sinkhorn_kernel(const float* __restrict__ logits,
                     const int* __restrict__ free_agents_num,
                     const int* __restrict__ tasks_num,
                     float* __restrict__ out)
{
    extern __shared__ __align__(16) unsigned char sm[];
    half2* E2   = reinterpret_cast<half2*>(sm);
    float* exch = reinterpret_cast<float*>(sm + OFF_EXCH);  // [buf][rank][256]
    float* u    = reinterpret_cast<float*>(sm + OFF_U);
    float* w    = reinterpret_cast<float*>(sm + OFF_W);

    const int rank = blockIdx.x & 1;
    const int b    = blockIdx.x >> 1;
    const int t    = threadIdx.x;
    const int na   = free_agents_num[b];
    const int nt   = tasks_num[b];
    const int row0 = rank * ROWS;

    const float4* __restrict__ L4 =
        reinterpret_cast<const float4*>(logits) + (size_t)b * 16384 + (size_t)rank * 8192;
    float4* __restrict__ O4 =
        reinterpret_cast<float4*>(out) + (size_t)b * 16384 + (size_t)rank * 8192;
    float2* __restrict__ O2 = reinterpret_cast<float2*>(O4);

    // Degenerate batch: both cluster CTAs share b -> both take this branch (barrier-safe).
    if (na == 0 || nt == 0) {
        float4 z = make_float4(0.f, 0.f, 0.f, 0.f);
        #pragma unroll
        for (int k = 0; k < 8192 / NTH; ++k)
            O4[t + k * NTH] = z;
        return;
    }

    // ---- Phase 1: HBM -> E(fp16) + FUSED iteration-0 row sums (w == 1) ----
    // scr uses exchange BUFFER 1 ([512..768)): the peer's earliest DSMEM stores go to
    // buffer 0, and it cannot reach buffer 1 before the it=0 cluster barrier (which we
    // must also reach) -> no race with scr.
    float* scr = exch + 512;
    #pragma unroll 4
    for (int k = 0; k < 8192 / NTH; ++k) {
        int idx = t + k * NTH;
        int i = idx >> 6;                  // 64 float4 per row; all 32 lanes share one row
        int j = (idx & 63) << 2;
        half2 h01 = __floats2half2_rn(0.f, 0.f);
        half2 h23 = h01;
        float se = 0.f;
        if ((row0 + i) < na && j < nt) {
            float4 v = L4[idx];
            float e0 = __expf(v.x);
            float e1 = (j + 1) < nt ? __expf(v.y) : 0.f;
            float e2 = (j + 2) < nt ? __expf(v.z) : 0.f;
            float e3 = (j + 3) < nt ? __expf(v.w) : 0.f;
            h01 = __floats2half2_rn(e0, e1);
            h23 = __floats2half2_rn(e2, e3);
            se = (e0 + e1) + (e2 + e3);    // fp32, pre-rounding (more accurate than a re-read)
        }
        half2* row = E2 + i * P2 + (j >> 1);
        row[0] = h01;
        row[1] = h23;
        // Warp-reduce se (all lanes same row i); unique (warp,k) -> (i, half) slot.
        se += __shfl_xor_sync(0xffffffffu, se, 16);
        se += __shfl_xor_sync(0xffffffffu, se, 8);
        se += __shfl_xor_sync(0xffffffffu, se, 4);
        se += __shfl_xor_sync(0xffffffffu, se, 2);
        se += __shfl_xor_sync(0xffffffffu, se, 1);
        if ((t & 31) == 0) scr[2 * i + ((t >> 5) & 1)] = se;
    }
    __syncthreads();
    if (t < 128) {
        float S = scr[2 * t] + scr[2 * t + 1];
        u[t] = ((row0 + t) < na) ? 1.0f / S : 0.f;
    }
    __syncthreads();

    // 4-way split, block-granular trimming (proven R13 structure).
    const int rrow = t >> 2, q = t & 3;
    const bool rvalid = (row0 + rrow) < na;
    const int ntp = (nt + 1) >> 1;
    const int nrl = min(max(na - row0, 0), ROWS);
    int Mr = (ntp > 8 * q) ? (((ntp - 8 * q - 1) >> 5) + 1) : 0;   // <= 4
    int Mc = (nrl > 8 * q) ? (((nrl - 8 * q - 1) >> 5) + 1) : 0;   // <= 4
    if (!rvalid) Mr = 0;
    if (2 * rrow >= nt) Mc = 0;

    unsigned raddr0;
    {
        unsigned laddr = (unsigned)__cvta_generic_to_shared(&exch[rank * 256 + 2 * rrow]);
        asm("mapa.shared::cluster.u32 %0, %1, %2;" : "=r"(raddr0) : "r"(laddr), "r"(rank ^ 1));
    }

    const half2*  Er = E2 + rrow * P2 + 8 * q;
    const float2* Wr = reinterpret_cast<const float2*>(w) + 8 * q;
    const half2*  Ec = E2 + (8 * q) * P2 + rrow;
    const float*  Uc = u + 8 * q;

    // 5 x (col-norm then row-norm), row-norm skipped on the last trip:
    // combined with the fused row-norm above = exactly 5 row + 5 col norms.
    for (int it = 0; it < ITERS; ++it) {
        const int bufo = (it & 1) * 512;

        // ---- Col pass: T_jp partial = sum_i E_i,jp * u_i ----
        float x0 = 0.f, y0 = 0.f, x1 = 0.f, y1 = 0.f;
        {
            const half2* p  = Ec;
            const float* up = Uc;
            for (int m = 0; m < Mc; ++m) {
                #pragma unroll
                for (int c = 0; c < 8; ++c) {
                    float2 e = __half22float2(p[c * P2]);
                    float uu = up[c];
                    if (c & 1) { x1 = fmaf(e.x, uu, x1); y1 = fmaf(e.y, uu, y1); }
                    else       { x0 = fmaf(e.x, uu, x0); y0 = fmaf(e.y, uu, y0); }
                }
                p += 32 * P2; up += 32;
            }
        }
        float ax = x0 + x1, ay = y0 + y1;
        ax += __shfl_xor_sync(0xffffffffu, ax, 1);
        ay += __shfl_xor_sync(0xffffffffu, ay, 1);
        ax += __shfl_xor_sync(0xffffffffu, ax, 2);
        ay += __shfl_xor_sync(0xffffffffu, ay, 2);
        if (q == 0) {
            exch[bufo + rank * 256 + 2 * rrow]     = ax;
            exch[bufo + rank * 256 + 2 * rrow + 1] = ay;
            unsigned ra = raddr0 + (unsigned)(bufo * 4);
            asm volatile("st.shared::cluster.f32 [%0],   %1;" :: "r"(ra), "f"(ax) : "memory");
            asm volatile("st.shared::cluster.f32 [%0+4], %1;" :: "r"(ra), "f"(ay) : "memory");
        }
        asm volatile("barrier.cluster.arrive.aligned;" ::: "memory");
        asm volatile("barrier.cluster.wait.aligned;"   ::: "memory");

        if (t < 128) {
            int j0 = 2 * t, j1 = j0 + 1;
            float T0 = exch[bufo + j0] + exch[bufo + 256 + j0];
            float T1 = exch[bufo + j1] + exch[bufo + 256 + j1];
            w[j0] = (j0 < nt) ? 1.0f / T0 : 0.f;
            w[j1] = (j1 < nt) ? 1.0f / T1 : 0.f;
        }
        __syncthreads();

        if (it < ITERS - 1) {
            // ---- Row pass: S_i = sum_j E_ij * w_j ----
            float a0 = 0.f, a1 = 0.f, a2 = 0.f, a3 = 0.f;
            {
                const half2*  p  = Er;
                const float2* wp = Wr;
                for (int m = 0; m < Mr; ++m) {
                    #pragma unroll
                    for (int c = 0; c < 8; ++c) {
                        float2 e  = __half22float2(p[c]);
                        float2 ww = wp[c];
                        if (c & 1) { a2 = fmaf(e.x, ww.x, a2); a3 = fmaf(e.y, ww.y, a3); }
                        else       { a0 = fmaf(e.x, ww.x, a0); a1 = fmaf(e.y, ww.y, a1); }
                    }
                    p += 32; wp += 32;
                }
            }
            float S = (a0 + a2) + (a1 + a3);
            S += __shfl_xor_sync(0xffffffffu, S, 1);
            S += __shfl_xor_sync(0xffffffffu, S, 2);
            if (q == 0) u[rrow] = rvalid ? 1.0f / S : 0.f;
            __syncthreads();
        }
    }

    // ---- Phase 3 (FIXED: exactly this CTA's 8192 float4): out = E*u*w*exp(1e-6) ----
    // Lane l handles cols {2(l+32s), 2(l+32s)+1} for s<4: E banks row + l + 32s -> all 32
    // lanes distinct, conflict-free. w hoisted to 8 registers, reused across 8 rows.
    {
        const float C = 1.0000010000005f;
        const int l = t & 31;
        float2 wr[4];
        #pragma unroll
        for (int s = 0; s < 4; ++s)
            wr[s] = *reinterpret_cast<const float2*>(w + 2 * (l + 32 * s));
        #pragma unroll 2
        for (int k = 0; k < 8; ++k) {
            int idx = t + k * NTH;         // < 4096
            int row = idx >> 5;            // < 128, warp-uniform
            if ((row0 + row) < na) {
                float ui = u[row] * C;
                #pragma unroll
                for (int s = 0; s < 4; ++s) {
                    float2 e = __half22float2(E2[row * P2 + l + 32 * s]);
                    O2[row * 128 + l + 32 * s] = make_float2(e.x * ui * wr[s].x,
                                                             e.y * ui * wr[s].y);
                }
            } else {
                float2 z2 = make_float2(0.f, 0.f);
                #pragma unroll
                for (int s = 0; s < 4; ++s)
                    O2[row * 128 + l + 32 * s] = z2;
            }
        }
    }
}

extern "C" void kernel_launch(void* const* d_in, const int* in_sizes, int n_in,
                              void* d_out, int out_size)
{
    const float* logits = (const float*)d_in[0];
    const int*   agents = (const int*)d_in[1];
    const int*   tasks  = (const int*)d_in[2];
    float*       out    = (float*)d_out;
    const int B = in_sizes[1];

    cudaFuncSetAttribute(sinkhorn_kernel,
                         cudaFuncAttributeMaxDynamicSharedMemorySize, SMEM_TOTAL);

    sinkhorn_kernel<<<2 * B, NTH, SMEM_TOTAL>>>(logits, agents, tasks, out);
}